// round 16
// baseline (speedup 1.0000x reference)
#include <cuda_runtime.h>
#include <math.h>

#define N_NODES 50000
#define D 100
#define E_EDGES 800000
#define OUTD 300

// Row layout (512B per node, 2 independent 256B halves, each 2 cache lines):
//   half h floats [0..49] = w*f[50h..50h+49], slot 50 = w (duplicated!), 51 = 0,
//   slots 52..63 untouched pad. A warp serves one half: 13 lanes x 16B = 208B,
//   exactly 2 aligned L1 lines. den accumulates from slot 50 -> no cross-warp
//   exchange needed in the gather loop.
// w = exp(score), score in [-1,1]: exp never overflows, so the reference's
// max-subtraction cancels exactly in the softmax ratio.
__device__ __align__(512) float g_gw[2][(size_t)N_NODES * 128];
__device__ __align__(16) float g_nrh[2][56];   // normalized nr halves, zeros at 50..55
__device__ __align__(16) int g_coff[E_EDGES + 32];   // col * 512 (byte offset)
__device__ int g_rowptr[N_NODES + 1];

typedef unsigned long long u64;

// ---------------------------------------------------------------------------
__device__ __forceinline__ void fadd2(u64& a, u64 b) {
    asm("add.rn.f32x2 %0, %0, %1;" : "+l"(a) : "l"(b));
}
__device__ __forceinline__ float2 unpack2(u64 v) {
    float2 r;
    asm("mov.b64 {%0, %1}, %2;" : "=f"(r.x), "=f"(r.y) : "l"(v));
    return r;
}
__device__ __forceinline__ float tanha(float x) {      // HW tanh approx
    float r;
    asm("tanh.approx.f32 %0, %1;" : "=f"(r) : "f"(x));
    return r;
}

// ---------------------------------------------------------------------------
// Prep: coff = col*512, CSR rowptr (rows sorted), block 0 builds g_nrh.
__global__ void prep_kernel(const int* __restrict__ adj,
                            const float* __restrict__ none_rel) {
    if (blockIdx.x == 0 && threadIdx.x < 128) {
        __shared__ float ssum[128];
        int t = threadIdx.x;
        float v = (t < D) ? none_rel[t] : 0.f;
        ssum[t] = v * v;
        __syncthreads();
        for (int s = 64; s > 0; s >>= 1) {
            if (t < s) ssum[t] += ssum[t + s];
            __syncthreads();
        }
        float inv = 1.f / fmaxf(sqrtf(ssum[0]), 1e-12f);
        if (t < 50) {
            g_nrh[0][t] = none_rel[t] * inv;
            g_nrh[1][t] = none_rel[50 + t] * inv;
        } else if (t < 56) {
            g_nrh[0][t] = 0.f;
            g_nrh[1][t] = 0.f;
        }
    }
    int i = blockIdx.x * blockDim.x + threadIdx.x;
    if (i < E_EDGES)
        g_coff[i] = adj[2 * i + 1] << 9;   // col * 512 bytes
    if (i <= N_NODES) {
        int lo = 0, hi = E_EDGES;
        while (lo < hi) {
            int mid = (lo + hi) >> 1;
            if (adj[2 * mid] < i) lo = mid + 1; else hi = mid;
        }
        g_rowptr[i] = lo;
    }
}

// ---------------------------------------------------------------------------
// Store this half's result chunk (lane l<12: f[4l..4l+3]; lane12: f[48],f[49])
// to out columns [50h, 50h+50). Half B columns are 8B-aligned only -> float2.
__device__ __forceinline__ void store_out(float4 r, int lane, int half,
                                          float* __restrict__ outp) {
    if (half == 0) {
        if (lane < 12) *(float4*)(outp + 4 * lane) = r;
        else if (lane == 12) *(float2*)(outp + 48) = make_float2(r.x, r.y);
    } else {
        if (lane < 12) {
            *(float2*)(outp + 50 + 4 * lane) = make_float2(r.x, r.y);
            *(float2*)(outp + 52 + 4 * lane) = make_float2(r.z, r.w);
        } else if (lane == 12) *(float2*)(outp + 98) = make_float2(r.x, r.y);
    }
}

// Store premultiplied half row [w*f.., w@50, 0@51] into g_gw[fbuf].
__device__ __forceinline__ void store_premult(float4 r, float w, int lane,
                                              int node, int half, int fbuf) {
    char* base = (char*)g_gw[fbuf] + ((size_t)node << 9) + (half << 8);
    if (lane < 12) {
        float4 s = make_float4(w * r.x, w * r.y, w * r.z, w * r.w);
        *(float4*)(base + 16 * lane) = s;
    } else if (lane == 12) {
        float4 s = make_float4(w * r.x, w * r.y, w, 0.f);
        *(float4*)(base + 192) = s;
    }
}

// Cross-warp epilogue: partial dot/ss per half-warp, combine via smem, then
// store premultiplied half. Called by ALL threads of the block (has barrier).
__device__ __forceinline__ void epilogue2(float4 r, int lane, int wib,
                                          int node, int half, int fbuf,
                                          float2* s_ds) {
    float dot = 0.f, ss = 0.f;
    if (lane < 13) {
        float4 nv = *(const float4*)(g_nrh[half] + 4 * lane);
        dot = r.x * nv.x + r.y * nv.y + r.z * nv.z + r.w * nv.w;
        ss  = r.x * r.x + r.y * r.y + r.z * r.z + r.w * r.w;
    }
    #pragma unroll
    for (int o = 16; o; o >>= 1) {
        dot += __shfl_xor_sync(0xffffffffu, dot, o);
        ss  += __shfl_xor_sync(0xffffffffu, ss, o);
    }
    if (lane == 0) s_ds[wib] = make_float2(dot, ss);
    __syncthreads();
    float2 p0 = s_ds[wib & ~1];
    float2 p1 = s_ds[wib | 1];
    float w = __expf(-(p0.x + p1.x) / fmaxf(sqrtf(p0.y + p1.y), 1e-12f));
    store_premult(r, w, lane, node, half, fbuf);
}

// ---------------------------------------------------------------------------
// Layer 0: 2 warps per node. tanh(features) -> out cols [0,100) + g_gw[0].
__global__ void __launch_bounds__(128) tanh_score_kernel(
        const float* __restrict__ feat, float* __restrict__ out) {
    __shared__ float2 s_ds[4];
    int wib = threadIdx.x >> 5;
    int gw = blockIdx.x * 4 + wib;
    int node = gw >> 1;
    int half = gw & 1;
    int lane = threadIdx.x & 31;
    const float* fb = feat + (size_t)node * D;

    float4 r = make_float4(0.f, 0.f, 0.f, 0.f);
    if (lane < 12) {
        if (half == 0) {
            float4 v = *(const float4*)(fb + 4 * lane);
            r.x = tanha(v.x); r.y = tanha(v.y); r.z = tanha(v.z); r.w = tanha(v.w);
        } else {
            float2 u0 = *(const float2*)(fb + 50 + 4 * lane);
            float2 u1 = *(const float2*)(fb + 52 + 4 * lane);
            r.x = tanha(u0.x); r.y = tanha(u0.y); r.z = tanha(u1.x); r.w = tanha(u1.y);
        }
    } else if (lane == 12) {
        float2 u = *(const float2*)(fb + 50 * half + 48);
        r.x = tanha(u.x); r.y = tanha(u.y);
    }
    store_out(r, lane, half, out + (size_t)node * OUTD);
    epilogue2(r, lane, wib, node, half, 0, s_ds);
}

// ---------------------------------------------------------------------------
// Attention row kernel: 2 warps per row, each gathers its 208B half per edge
// (2 L1 lines), with the light 2-stage pipeline over 4-edge batches.
template <bool LAST>
__global__ void __launch_bounds__(128) row_kernel(int buf, float* __restrict__ out,
                                                  int outoff) {
    __shared__ float2 s_ds[4];
    int wib = threadIdx.x >> 5;
    int gw = blockIdx.x * 4 + wib;
    int node = gw >> 1;
    int half = gw & 1;
    int lane = threadIdx.x & 31;
    int beg = g_rowptr[node];
    int end = g_rowptr[node + 1];
    const char* __restrict__ gwb = (const char*)g_gw[buf] + (half << 8);
    bool act = (lane < 13);
    int laneoff = lane * 16;

    u64 a0 = 0ull, a1 = 0ull;

    int e = beg;
    int pre = (4 - (beg & 3)) & 3;
    if (pre > end - beg) pre = end - beg;
    for (int k = 0; k < pre; ++k, ++e) {
        if (act) {
            ulonglong2 v = *(const ulonglong2*)(gwb + g_coff[e] + laneoff);
            fadd2(a0, v.x); fadd2(a1, v.y);
        }
    }
    if (e + 4 <= end) {
        ulonglong2 cv0, cv1, cv2, cv3;
        {
            int4 q = *(const int4*)(g_coff + e);
            if (act) {
                cv0 = *(const ulonglong2*)(gwb + q.x + laneoff);
                cv1 = *(const ulonglong2*)(gwb + q.y + laneoff);
                cv2 = *(const ulonglong2*)(gwb + q.z + laneoff);
                cv3 = *(const ulonglong2*)(gwb + q.w + laneoff);
            }
        }
        e += 4;
        for (; e + 4 <= end; e += 4) {
            int4 q = *(const int4*)(g_coff + e);
            ulonglong2 nv0, nv1, nv2, nv3;
            if (act) {
                nv0 = *(const ulonglong2*)(gwb + q.x + laneoff);
                nv1 = *(const ulonglong2*)(gwb + q.y + laneoff);
                nv2 = *(const ulonglong2*)(gwb + q.z + laneoff);
                nv3 = *(const ulonglong2*)(gwb + q.w + laneoff);
                fadd2(a0, cv0.x); fadd2(a1, cv0.y);
                fadd2(a0, cv1.x); fadd2(a1, cv1.y);
                fadd2(a0, cv2.x); fadd2(a1, cv2.y);
                fadd2(a0, cv3.x); fadd2(a1, cv3.y);
                cv0 = nv0; cv1 = nv1; cv2 = nv2; cv3 = nv3;
            }
        }
        if (act) {
            fadd2(a0, cv0.x); fadd2(a1, cv0.y);
            fadd2(a0, cv1.x); fadd2(a1, cv1.y);
            fadd2(a0, cv2.x); fadd2(a1, cv2.y);
            fadd2(a0, cv3.x); fadd2(a1, cv3.y);
        }
    }
    for (; e < end; ++e) {
        if (act) {
            ulonglong2 v = *(const ulonglong2*)(gwb + g_coff[e] + laneoff);
            fadd2(a0, v.x); fadd2(a1, v.y);
        }
    }

    // lane 12's a1 = (sum of w, 0) -> den (identical in both half-warps).
    float den = __shfl_sync(0xffffffffu, unpack2(a1).x, 12);
    float inv = (end > beg) ? (1.f / den) : 0.f;

    float2 lo = unpack2(a0);
    float2 hi = unpack2(a1);
    float4 r = make_float4(0.f, 0.f, 0.f, 0.f);
    if (lane < 12) {
        r.x = tanha(lo.x * inv);
        r.y = tanha(lo.y * inv);
        r.z = tanha(hi.x * inv);
        r.w = tanha(hi.y * inv);
    } else if (lane == 12) {
        r.x = tanha(lo.x * inv);
        r.y = tanha(lo.y * inv);
    }
    store_out(r, lane, half, out + (size_t)node * OUTD + outoff);
    if (!LAST)
        epilogue2(r, lane, wib, node, half, buf ^ 1, s_ds);
}

// ---------------------------------------------------------------------------
extern "C" void kernel_launch(void* const* d_in, const int* in_sizes, int n_in,
                              void* d_out, int out_size) {
    const float* features = (const float*)d_in[0];
    // d_in[1] = rel_emb: unused by the reference computation.
    const int* adj        = (const int*)d_in[2];   // int32 pairs (JAX demotes int64)
    const float* none_rel = (const float*)d_in[3];
    float* out = (float*)d_out;

    prep_kernel<<<(E_EDGES + 255) / 256, 256>>>(adj, none_rel);
    const int NB = N_NODES / 2;          // 2 nodes x 2 half-warps per 128-thr block
    tanh_score_kernel<<<NB, 128>>>(features, out);
    row_kernel<false><<<NB, 128>>>(0, out, D);
    row_kernel<true ><<<NB, 128>>>(1, out, 2 * D);
}

// round 17
// speedup vs baseline: 1.5216x; 1.5216x over previous
#include <cuda_runtime.h>
#include <cuda_fp16.h>
#include <math.h>

#define N_NODES 50000
#define D 100
#define E_EDGES 800000
#define OUTD 300

// Row c of g_h[b] (256B stride, line-aligned): halves 0..99 = fp16(w_c*f_c[j]),
// halves 100..101 = w_c as one fp32 word, 102..103 = 0, rest pad.
// Lane l (0..24) loads halves [4l,4l+4) = 8B; lane 25 loads the w word.
// 26 lanes x 8B = 208B = 2 aligned L1 lines per edge (vs 4 for fp32).
// w = exp(score), score in [-1,1]: exp never overflows, so the reference's
// max-subtraction cancels exactly in the softmax ratio. den stays fp32-exact.
__device__ __align__(256) __half g_h[2][(size_t)N_NODES * 128];
__device__ __align__(16) float g_nr[128];
__device__ __align__(16) int g_coff[E_EDGES + 32];   // col * 256 (byte offset)
__device__ int g_rowptr[N_NODES + 1];

typedef unsigned long long u64;

// ---------------------------------------------------------------------------
__device__ __forceinline__ void fadd2(u64& a, u64 b) {
    asm("add.rn.f32x2 %0, %0, %1;" : "+l"(a) : "l"(b));
}
__device__ __forceinline__ float2 unpack2(u64 v) {
    float2 r;
    asm("mov.b64 {%0, %1}, %2;" : "=f"(r.x), "=f"(r.y) : "l"(v));
    return r;
}
__device__ __forceinline__ u64 pack2(float x, float y) {
    u64 r;
    asm("mov.b64 %0, {%1, %2};" : "=l"(r) : "f"(x), "f"(y));
    return r;
}
__device__ __forceinline__ void hacc(unsigned int& a, unsigned int b) { // half2 +=
    __half2 ha = *(__half2*)&a;
    __half2 hb = *(__half2*)&b;
    ha = __hadd2(ha, hb);
    a = *(unsigned int*)&ha;
}
__device__ __forceinline__ float tanha(float x) {      // HW tanh approx
    float r;
    asm("tanh.approx.f32 %0, %1;" : "=f"(r) : "f"(x));
    return r;
}

// ---------------------------------------------------------------------------
// Prep: coff = col*256, CSR rowptr (rows sorted), block 0 builds g_nr.
__global__ void prep_kernel(const int* __restrict__ adj,
                            const float* __restrict__ none_rel) {
    if (blockIdx.x == 0 && threadIdx.x < 128) {
        __shared__ float ssum[128];
        int t = threadIdx.x;
        float v = (t < D) ? none_rel[t] : 0.f;
        ssum[t] = v * v;
        __syncthreads();
        for (int s = 64; s > 0; s >>= 1) {
            if (t < s) ssum[t] += ssum[t + s];
            __syncthreads();
        }
        float inv = 1.f / fmaxf(sqrtf(ssum[0]), 1e-12f);
        g_nr[t] = (t < D) ? v * inv : 0.f;
    }
    int i = blockIdx.x * blockDim.x + threadIdx.x;
    if (i < E_EDGES)
        g_coff[i] = adj[2 * i + 1] << 8;   // col * 256 bytes
    if (i <= N_NODES) {
        int lo = 0, hi = E_EDGES;
        while (lo < hi) {
            int mid = (lo + hi) >> 1;
            if (adj[2 * mid] < i) lo = mid + 1; else hi = mid;
        }
        g_rowptr[i] = lo;
    }
}

// ---------------------------------------------------------------------------
// Warp-collective epilogue: r = fp32 feature chunk f[4l..4l+3] on lanes 0..24.
// w = exp(-dot(l2norm(f), nr)). Store fp16 premult row + fp32 w + zero pad.
__device__ __forceinline__ void epilogue_store(float4 r, int lane, int node, int fbuf) {
    float dot = 0.f, ss = 0.f;
    if (lane < 25) {
        float4 nv = *(const float4*)(g_nr + lane * 4);
        dot = r.x * nv.x + r.y * nv.y + r.z * nv.z + r.w * nv.w;
        ss  = r.x * r.x + r.y * r.y + r.z * r.z + r.w * r.w;
    }
    #pragma unroll
    for (int o = 16; o; o >>= 1) {
        dot += __shfl_xor_sync(0xffffffffu, dot, o);
        ss  += __shfl_xor_sync(0xffffffffu, ss, o);
    }
    float w = __expf(-dot / fmaxf(sqrtf(ss), 1e-12f));
    char* row = (char*)g_h[fbuf] + ((size_t)node << 8);
    if (lane < 25) {
        __half2 p0 = __floats2half2_rn(w * r.x, w * r.y);
        __half2 p1 = __floats2half2_rn(w * r.z, w * r.w);
        uint2 u;
        u.x = *(unsigned int*)&p0;
        u.y = *(unsigned int*)&p1;
        *(uint2*)(row + 8 * lane) = u;
    } else if (lane == 25) {
        uint2 u;
        u.x = __float_as_uint(w);   // halves 100..101
        u.y = 0u;                   // halves 102..103 = 0
        *(uint2*)(row + 200) = u;
    }
}

// ---------------------------------------------------------------------------
// Layer 0: r = tanh(features); write out cols [0,D), build g_h[0].
__global__ void tanh_score_kernel(const float* __restrict__ feat,
                                  float* __restrict__ out) {
    int node = (blockIdx.x * blockDim.x + threadIdx.x) >> 5;
    int lane = threadIdx.x & 31;
    if (node >= N_NODES) return;
    float4 r = make_float4(0.f, 0.f, 0.f, 0.f);
    if (lane < 25) {
        float4 v = *(const float4*)(feat + (size_t)node * D + lane * 4);
        r.x = tanha(v.x); r.y = tanha(v.y); r.z = tanha(v.z); r.w = tanha(v.w);
        *(float4*)(out + (size_t)node * OUTD + lane * 4) = r;
    }
    epilogue_store(r, lane, node, 0);
}

// ---------------------------------------------------------------------------
// Attention row kernel: fp16 gather-sum, 208B = 2 L1 lines per edge.
// Lanes 0..24: 2 HADD2 per edge; lane 25 accumulates fp32 den.
// half2 accumulators flushed to packed-fp32 every 8 edges (bounded chains).
template <bool LAST>
__global__ void __launch_bounds__(128) row_kernel(int buf, float* __restrict__ out,
                                                  int outoff) {
    int row = (blockIdx.x * blockDim.x + threadIdx.x) >> 5;
    int lane = threadIdx.x & 31;
    if (row >= N_NODES) return;
    int beg = g_rowptr[row];
    int end = g_rowptr[row + 1];
    const char* __restrict__ hb = (const char*)g_h[buf];
    bool feat_lane = (lane < 25);
    bool den_lane = (lane == 25);
    int laneoff = lane * 8;

    u64 a0 = 0ull, a1 = 0ull;            // fp32 packed accumulators
    unsigned int h0 = 0u, h1 = 0u;       // fp16 half2 accumulators
    float den = 0.f;                     // lane 25

#define EDGE(v) do {                                                          \
        if (feat_lane) { hacc(h0, (v).x); hacc(h1, (v).y); }                  \
        else if (den_lane) den += __uint_as_float((v).x);                     \
    } while (0)
#define FLUSH() do {                                                          \
        float2 f0 = __half22float2(*(__half2*)&h0);                           \
        float2 f1 = __half22float2(*(__half2*)&h1);                           \
        fadd2(a0, pack2(f0.x, f0.y));                                         \
        fadd2(a1, pack2(f1.x, f1.y));                                         \
        h0 = h1 = 0u;                                                         \
    } while (0)

    int e = beg;
    // Peel to int4-aligned coff reads, then flush.
    int pre = (4 - (beg & 3)) & 3;
    if (pre > end - beg) pre = end - beg;
    for (int k = 0; k < pre; ++k, ++e) {
        if (lane < 26) {
            uint2 v = *(const uint2*)(hb + g_coff[e] + laneoff);
            EDGE(v);
        }
    }
    if (pre) FLUSH();

    // Main: 8 edges per iteration, loads batched before consumption.
    for (; e + 8 <= end; e += 8) {
        int4 qa = *(const int4*)(g_coff + e);
        int4 qb = *(const int4*)(g_coff + e + 4);
        if (lane < 26) {
            uint2 v0 = *(const uint2*)(hb + qa.x + laneoff);
            uint2 v1 = *(const uint2*)(hb + qa.y + laneoff);
            uint2 v2 = *(const uint2*)(hb + qa.z + laneoff);
            uint2 v3 = *(const uint2*)(hb + qa.w + laneoff);
            uint2 v4 = *(const uint2*)(hb + qb.x + laneoff);
            uint2 v5 = *(const uint2*)(hb + qb.y + laneoff);
            uint2 v6 = *(const uint2*)(hb + qb.z + laneoff);
            uint2 v7 = *(const uint2*)(hb + qb.w + laneoff);
            EDGE(v0); EDGE(v1); EDGE(v2); EDGE(v3);
            EDGE(v4); EDGE(v5); EDGE(v6); EDGE(v7);
        }
        FLUSH();
    }
    // Tail (<8 edges), then final flush (chain <= 7).
    for (; e < end; ++e) {
        if (lane < 26) {
            uint2 v = *(const uint2*)(hb + g_coff[e] + laneoff);
            EDGE(v);
        }
    }
    FLUSH();
#undef EDGE
#undef FLUSH

    den = __shfl_sync(0xffffffffu, den, 25);
    float inv = (end > beg) ? (1.f / den) : 0.f;

    float2 lo = unpack2(a0);
    float2 hi = unpack2(a1);
    float4 r = make_float4(0.f, 0.f, 0.f, 0.f);
    if (lane < 25) {
        r.x = tanha(lo.x * inv);
        r.y = tanha(lo.y * inv);
        r.z = tanha(hi.x * inv);
        r.w = tanha(hi.y * inv);
        *(float4*)(out + (size_t)row * OUTD + outoff + lane * 4) = r;
    }
    if (!LAST)
        epilogue_store(r, lane, row, buf ^ 1);
}

// ---------------------------------------------------------------------------
extern "C" void kernel_launch(void* const* d_in, const int* in_sizes, int n_in,
                              void* d_out, int out_size) {
    const float* features = (const float*)d_in[0];
    // d_in[1] = rel_emb: unused by the reference computation.
    const int* adj        = (const int*)d_in[2];   // int32 pairs (JAX demotes int64)
    const float* none_rel = (const float*)d_in[3];
    float* out = (float*)d_out;

    prep_kernel<<<(E_EDGES + 255) / 256, 256>>>(adj, none_rel);
    tanh_score_kernel<<<(N_NODES * 32 + 255) / 256, 256>>>(features, out);
    const int RB = (N_NODES * 32 + 127) / 128;
    row_kernel<false><<<RB, 128>>>(0, out, D);
    row_kernel<true ><<<RB, 128>>>(1, out, 2 * D);
}